// round 1
// baseline (speedup 1.0000x reference)
#include <cuda_runtime.h>
#include <math.h>
#include <stdint.h>

// Fixed problem shapes (from reference setup_inputs)
#define NMAX 262144
#define EMAX 4194304

// ---------------- scratch (device globals; no allocation allowed) ------------
__device__ float    g_h1[2 * NMAX];    // conv1 accumulators, then elu(h1) in-place
__device__ float    g_cnt[NMAX];       // dst degree (shared by both convs)
__device__ float    g_h2[4 * NMAX];    // conv2 accumulators, then mean in-place
__device__ double   g_stats[12];       // sum1[2], sumsq1[2], sum2[4], sumsq2[4]
__device__ float    g_scale1[2], g_shift1[2];
__device__ float    g_scale2[4], g_shift2[4];
__device__ unsigned g_pool[64];        // 16 cells x 4 channels, ordered-uint max
__device__ int      g_idx64;           // 1 if edge_index is int64, 0 if int32

// ordered-uint encoding so unsigned atomicMax == float max
__device__ __forceinline__ unsigned fenc(float f) {
    unsigned u = __float_as_uint(f);
    return (u & 0x80000000u) ? ~u : (u | 0x80000000u);
}
__device__ __forceinline__ float fdec(unsigned u) {
    return (u & 0x80000000u) ? __uint_as_float(u & 0x7FFFFFFFu)
                             : __uint_as_float(~u);
}
#define ENC_NEG_INF 0x007FFFFFu  // fenc(-inf)

// ---------------- prelude: init pool slots + sniff index dtype ---------------
__global__ void k_prelude(const unsigned* __restrict__ eidx_words, int E) {
    int t = threadIdx.x;
    if (t < 64) g_pool[t] = ENC_NEG_INF;
    if (t == 0) {
        // If data is int64 little-endian with values < 2^31, every odd 32-bit
        // word is 0. For int32 data those words are random indices — the
        // probability all 64 are zero is ~(1/N)^64.
        int is64 = 1;
        int nchk = (E < 64) ? E : 64;
        for (int i = 0; i < nchk; i++)
            if (eidx_words[2 * i + 1] != 0u) { is64 = 0; break; }
        g_idx64 = is64;
    }
}

// ---------------- spline basis helper (general K=2 path) ---------------------
struct Basis {
    float fr[3], gr[3];
    int   i0[3], i1[3];
};
__device__ __forceinline__ Basis make_basis(const float* __restrict__ attr, int e) {
    Basis b;
#pragma unroll
    for (int d = 0; d < 3; d++) {
        float v  = __ldg(&attr[3 * e + d]);   // v = pseudo * (K-1), K=2
        float lo = floorf(v);
        b.fr[d] = v - lo;
        b.gr[d] = 1.0f - b.fr[d];
        int l    = (int)lo;
        b.i0[d] = min(max(l, 0), 1);
        b.i1[d] = min(max(l + 1, 0), 1);
    }
    return b;
}

__device__ __forceinline__ void load_edge(const void* eidx, int e, int E, int is64,
                                          int& src, int& dst) {
    if (is64) {
        const long long* p = (const long long*)eidx;
        src = (int)__ldg(&p[e]);
        dst = (int)__ldg(&p[(long long)E + e]);
    } else {
        const int* p = (const int*)eidx;
        src = __ldg(&p[e]);
        dst = __ldg(&p[E + e]);
    }
}

// ---------------- conv1: x[N,1] x W1[8,1,2] -> scatter-add [N,2] + degree ----
__global__ void k_conv1(const float* __restrict__ x, const void* __restrict__ eidx,
                        const float* __restrict__ attr, const float* __restrict__ W1,
                        int E) {
    __shared__ float sW[16];
    __shared__ int   sI64;
    int t = threadIdx.x;
    if (t < 16) sW[t] = W1[t];
    if (t == 0) sI64 = g_idx64;
    __syncthreads();

    int e = blockIdx.x * 256 + t;
    if (e >= E) return;

    int src, dst;
    load_edge(eidx, e, E, sI64, src, dst);
    Basis bs = make_basis(attr, e);

    float a0 = 0.f, a1 = 0.f;
#pragma unroll
    for (int b = 0; b < 8; b++) {
        float w = ((b & 1) ? bs.fr[0] : bs.gr[0]) *
                  ((b & 2) ? bs.fr[1] : bs.gr[1]) *
                  ((b & 4) ? bs.fr[2] : bs.gr[2]);
        int idx = ((b & 1) ? bs.i1[0] : bs.i0[0]) +
              2 * ((b & 2) ? bs.i1[1] : bs.i0[1]) +
              4 * ((b & 4) ? bs.i1[2] : bs.i0[2]);
        a0 = fmaf(w, sW[2 * idx + 0], a0);
        a1 = fmaf(w, sW[2 * idx + 1], a1);
    }
    float xs = __ldg(&x[src]);
    a0 *= xs; a1 *= xs;

    float* p2 = &g_h1[2 * dst];
    asm volatile("red.global.add.v2.f32 [%0], {%1, %2};"
                 :: "l"(p2), "f"(a0), "f"(a1) : "memory");
    asm volatile("red.global.add.f32 [%0], %1;"
                 :: "l"(&g_cnt[dst]), "f"(1.0f) : "memory");
}

// ---------------- finish1: mean -> ELU -> store + BN1 stats ------------------
__global__ void k_finish1(int N) {
    int n = blockIdx.x * 256 + threadIdx.x;
    float a = 0.f, b = 0.f;
    if (n < N) {
        float inv = 1.0f / fmaxf(g_cnt[n], 1.0f);
        a = g_h1[2 * n + 0] * inv;
        b = g_h1[2 * n + 1] * inv;
        a = (a > 0.f) ? a : expm1f(a);   // ELU, alpha=1
        b = (b > 0.f) ? b : expm1f(b);
        g_h1[2 * n + 0] = a;
        g_h1[2 * n + 1] = b;
    }
    float s0 = a, s1 = b, s2 = a * a, s3 = b * b;
#pragma unroll
    for (int o = 16; o; o >>= 1) {
        s0 += __shfl_down_sync(~0u, s0, o);
        s1 += __shfl_down_sync(~0u, s1, o);
        s2 += __shfl_down_sync(~0u, s2, o);
        s3 += __shfl_down_sync(~0u, s3, o);
    }
    if ((threadIdx.x & 31) == 0) {
        atomicAdd(&g_stats[0], (double)s0);
        atomicAdd(&g_stats[1], (double)s1);
        atomicAdd(&g_stats[2], (double)s2);
        atomicAdd(&g_stats[3], (double)s3);
    }
}

// ---------------- BN params: scale = gamma*rsqrt(var+eps), shift -------------
__global__ void k_bnparams(const float* __restrict__ gamma, const float* __restrict__ beta,
                           int N, int C, int off, int which) {
    int t = threadIdx.x;
    if (t < C) {
        double invN = 1.0 / (double)N;
        double mu   = g_stats[off + t] * invN;
        double var  = g_stats[off + C + t] * invN - mu * mu;
        float  sc   = (float)((double)gamma[t] / sqrt(var + 1e-5));
        float  sh   = beta[t] - (float)mu * sc;
        if (which == 0) { g_scale1[t] = sc; g_shift1[t] = sh; }
        else            { g_scale2[t] = sc; g_shift2[t] = sh; }
    }
}

// ---------------- conv2: BN1(h1)[N,2] x W2[8,2,4] -> scatter-add [N,4] -------
__global__ void k_conv2(const void* __restrict__ eidx, const float* __restrict__ attr,
                        const float* __restrict__ W2, int E) {
    __shared__ float sW[64];
    __shared__ float sSc[2], sSh[2];
    __shared__ int   sI64;
    int t = threadIdx.x;
    if (t < 64) sW[t] = W2[t];
    if (t < 2)  { sSc[t] = g_scale1[t]; sSh[t] = g_shift1[t]; }
    if (t == 0) sI64 = g_idx64;
    __syncthreads();

    int e = blockIdx.x * 256 + t;
    if (e >= E) return;

    int src, dst;
    load_edge(eidx, e, E, sI64, src, dst);
    Basis bs = make_basis(attr, e);

    float2 h  = *(const float2*)&g_h1[2 * src];   // L2-resident gather (2MB)
    float  h0 = fmaf(h.x, sSc[0], sSh[0]);        // fused BN1
    float  h1 = fmaf(h.y, sSc[1], sSh[1]);

    float acc0 = 0.f, acc1 = 0.f, acc2 = 0.f, acc3 = 0.f;
#pragma unroll
    for (int b = 0; b < 8; b++) {
        float w = ((b & 1) ? bs.fr[0] : bs.gr[0]) *
                  ((b & 2) ? bs.fr[1] : bs.gr[1]) *
                  ((b & 4) ? bs.fr[2] : bs.gr[2]);
        int idx = ((b & 1) ? bs.i1[0] : bs.i0[0]) +
              2 * ((b & 2) ? bs.i1[1] : bs.i0[1]) +
              4 * ((b & 4) ? bs.i1[2] : bs.i0[2]);
        const float* Wb = &sW[8 * idx];           // W2[idx][i][o] = idx*8 + i*4 + o
        acc0 = fmaf(w, fmaf(h0, Wb[0], h1 * Wb[4]), acc0);
        acc1 = fmaf(w, fmaf(h0, Wb[1], h1 * Wb[5]), acc1);
        acc2 = fmaf(w, fmaf(h0, Wb[2], h1 * Wb[6]), acc2);
        acc3 = fmaf(w, fmaf(h0, Wb[3], h1 * Wb[7]), acc3);
    }
    asm volatile("red.global.add.v4.f32 [%0], {%1, %2, %3, %4};"
                 :: "l"(&g_h2[4 * dst]), "f"(acc0), "f"(acc1), "f"(acc2), "f"(acc3)
                 : "memory");
}

// ---------------- finish2: mean -> store + BN2 stats -------------------------
__global__ void k_finish2(int N) {
    int n = blockIdx.x * 256 + threadIdx.x;
    float m[4] = {0.f, 0.f, 0.f, 0.f};
    if (n < N) {
        float inv = 1.0f / fmaxf(g_cnt[n], 1.0f);
#pragma unroll
        for (int o = 0; o < 4; o++) {
            m[o] = g_h2[4 * n + o] * inv;
            g_h2[4 * n + o] = m[o];
        }
    }
    float s[8];
#pragma unroll
    for (int o = 0; o < 4; o++) { s[o] = m[o]; s[4 + o] = m[o] * m[o]; }
#pragma unroll
    for (int o = 16; o; o >>= 1)
#pragma unroll
        for (int k = 0; k < 8; k++) s[k] += __shfl_down_sync(~0u, s[k], o);
    if ((threadIdx.x & 31) == 0) {
#pragma unroll
        for (int k = 0; k < 8; k++)
            atomicAdd(&g_stats[4 + k], (double)s[k]);
    }
}

// ---------------- pool: BN2 fused, 4x4 grid max into 64 slots ----------------
__global__ void k_pool(const float* __restrict__ pos, int N) {
    __shared__ unsigned smax[64];
    int t = threadIdx.x;
    if (t < 64) smax[t] = ENC_NEG_INF;
    __syncthreads();

    int n = blockIdx.x * 256 + t;
    if (n < N) {
        float px = __ldg(&pos[2 * n]);
        float py = __ldg(&pos[2 * n + 1]);
        int cx = min(max((int)floorf(px / 25.0f), 0), 3);
        int cy = min(max((int)floorf(py / 25.0f), 0), 3);
        int cl = cx + 4 * cy;
#pragma unroll
        for (int o = 0; o < 4; o++) {
            float v = fmaf(g_h2[4 * n + o], g_scale2[o], g_shift2[o]);
            atomicMax(&smax[4 * cl + o], fenc(v));
        }
    }
    __syncthreads();
    if (t < 64) atomicMax(&g_pool[t], smax[t]);
}

// ---------------- fc: [1,64] @ fc_w.T -> [1,4] -------------------------------
__global__ void k_fc(const float* __restrict__ fcw, float* __restrict__ out) {
    __shared__ float v[64];
    int t = threadIdx.x;
    if (t < 64) {
        float f = fdec(g_pool[t]);
        v[t] = isfinite(f) ? f : 0.0f;   // empty cells -> 0
    }
    __syncthreads();
    int w = t >> 5, l = t & 31;
    float p = v[l] * fcw[w * 64 + l] + v[l + 32] * fcw[w * 64 + l + 32];
#pragma unroll
    for (int o = 16; o; o >>= 1) p += __shfl_down_sync(~0u, p, o);
    if (l == 0) out[w] = p;
}

// ---------------- host launcher (graph-capturable, default stream) -----------
extern "C" void kernel_launch(void* const* d_in, const int* in_sizes, int n_in,
                              void* d_out, int out_size) {
    const float* x      = (const float*)d_in[0];
    const void*  eidx   = d_in[1];
    const float* attr   = (const float*)d_in[2];
    const float* pos    = (const float*)d_in[3];
    const float* W1     = (const float*)d_in[4];
    const float* W2     = (const float*)d_in[5];
    const float* gamma1 = (const float*)d_in[6];
    const float* beta1  = (const float*)d_in[7];
    const float* gamma2 = (const float*)d_in[8];
    const float* beta2  = (const float*)d_in[9];
    const float* fcw    = (const float*)d_in[10];
    float*       out    = (float*)d_out;

    int N = in_sizes[0];        // x is [N,1]
    int E = in_sizes[2] / 3;    // edge_attr is [E,3]

    void *ph1, *pcnt, *ph2, *pstats;
    cudaGetSymbolAddress(&ph1,   g_h1);
    cudaGetSymbolAddress(&pcnt,  g_cnt);
    cudaGetSymbolAddress(&ph2,   g_h2);
    cudaGetSymbolAddress(&pstats, g_stats);

    cudaMemsetAsync(ph1,   0, (size_t)2 * N * sizeof(float));
    cudaMemsetAsync(pcnt,  0, (size_t)N * sizeof(float));
    cudaMemsetAsync(ph2,   0, (size_t)4 * N * sizeof(float));
    cudaMemsetAsync(pstats, 0, 12 * sizeof(double));

    int ebl = (E + 255) / 256;
    int nbl = (N + 255) / 256;

    k_prelude<<<1, 64>>>((const unsigned*)eidx, E);
    k_conv1<<<ebl, 256>>>(x, eidx, attr, W1, E);
    k_finish1<<<nbl, 256>>>(N);
    k_bnparams<<<1, 32>>>(gamma1, beta1, N, 2, 0, 0);
    k_conv2<<<ebl, 256>>>(eidx, attr, W2, E);
    k_finish2<<<nbl, 256>>>(N);
    k_bnparams<<<1, 32>>>(gamma2, beta2, N, 4, 4, 1);
    k_pool<<<nbl, 256>>>(pos, N);
    k_fc<<<1, 128>>>(fcw, out);
}